// round 1
// baseline (speedup 1.0000x reference)
#include <cuda_runtime.h>
#include <math.h>

#define B_      8
#define C_      192
#define C3      576
#define HW      16384
#define HEADS_  4
#define HC      48
#define NCHUNK  128
#define NCHUNKS (HW / NCHUNK)   // 128
#define PART_STRIDE 2400        // 2304 gram + 48 nq + 48 nk

// -------- device scratch (no allocations allowed) --------
__device__ float g_qkv [(size_t)B_ * C3 * HW];     // 1x1 conv output
__device__ float g_dwq [(size_t)B_ * C3 * HW];     // depthwise output (q|k|v)
__device__ float g_part[(size_t)NCHUNKS * 32 * PART_STRIDE];
__device__ float g_gram[32 * HC * HC];
__device__ float g_nq  [32 * HC];
__device__ float g_nk  [32 * HC];
__device__ float g_attn[32 * HC * HC];
__device__ float g_weff[B_ * C_ * C_];

// ============================================================
// Generic GEMM: C[b] = A[b] (MxK, row major) @ B[b] (KxN, row major)
// BM=96, BN=128, BK=8, 256 threads, 6x8 micro-tile. N fixed = HW.
// M must be a multiple of 96, K a multiple of 8 (576/192 -> exact).
// ============================================================
__global__ __launch_bounds__(256) void gemm96x128(
    const float* __restrict__ A, const float* __restrict__ B,
    float* __restrict__ C, int K,
    size_t sAb, size_t sBb, size_t sCb)
{
    const int N = HW;
    A += (size_t)blockIdx.z * sAb;
    B += (size_t)blockIdx.z * sBb;
    C += (size_t)blockIdx.z * sCb;
    const int m0 = blockIdx.y * 96;
    const int n0 = blockIdx.x * 128;

    __shared__ float As[8][96];
    __shared__ float Bs[8][128];

    const int tid = threadIdx.x;
    const int am = tid >> 1;            // 0..95  (A row within tile)
    const int ak = (tid & 1) << 2;      // 0 or 4 (A k offset)
    const int bk = tid >> 5;            // 0..7
    const int bn = (tid & 31) << 2;     // 0..124
    const int tm = (tid >> 4) * 6;      // 0..90
    const int tn = (tid & 15) << 3;     // 0..120

    float acc[6][8];
#pragma unroll
    for (int i = 0; i < 6; i++)
#pragma unroll
        for (int j = 0; j < 8; j++) acc[i][j] = 0.f;

    for (int k0 = 0; k0 < K; k0 += 8) {
        if (tid < 192) {
            float4 av = *(const float4*)&A[(size_t)(m0 + am) * K + k0 + ak];
            As[ak + 0][am] = av.x;
            As[ak + 1][am] = av.y;
            As[ak + 2][am] = av.z;
            As[ak + 3][am] = av.w;
        }
        *(float4*)&Bs[bk][bn] = *(const float4*)&B[(size_t)(k0 + bk) * N + n0 + bn];
        __syncthreads();

#pragma unroll
        for (int kk = 0; kk < 8; kk++) {
            float a[6], b[8];
            *(float2*)&a[0] = *(float2*)&As[kk][tm + 0];
            *(float2*)&a[2] = *(float2*)&As[kk][tm + 2];
            *(float2*)&a[4] = *(float2*)&As[kk][tm + 4];
            *(float4*)&b[0] = *(float4*)&Bs[kk][tn + 0];
            *(float4*)&b[4] = *(float4*)&Bs[kk][tn + 4];
#pragma unroll
            for (int i = 0; i < 6; i++)
#pragma unroll
                for (int j = 0; j < 8; j++)
                    acc[i][j] += a[i] * b[j];
        }
        __syncthreads();
    }

#pragma unroll
    for (int i = 0; i < 6; i++) {
        size_t row = (size_t)(m0 + tm + i) * N + n0 + tn;
        *(float4*)&C[row]     = make_float4(acc[i][0], acc[i][1], acc[i][2], acc[i][3]);
        *(float4*)&C[row + 4] = make_float4(acc[i][4], acc[i][5], acc[i][6], acc[i][7]);
    }
}

// ============================================================
// Depthwise 3x3, SAME padding (cross-correlation, OIHW weights, I=1)
// ============================================================
__global__ __launch_bounds__(256) void dwconv_kernel(const float* __restrict__ wdw)
{
    const int p  = blockIdx.x * 256 + threadIdx.x;  // 0..16383
    const int ch = blockIdx.y;                      // 0..575
    const int b  = blockIdx.z;
    const int x  = p & 127;
    const int y  = p >> 7;

    const float* in = g_qkv + ((size_t)b * C3 + ch) * HW;
    const float* w  = wdw + ch * 9;

    float s = 0.f;
#pragma unroll
    for (int ky = 0; ky < 3; ky++) {
        const int yy = y + ky - 1;
        if (yy < 0 || yy > 127) continue;
#pragma unroll
        for (int kx = 0; kx < 3; kx++) {
            const int xx = x + kx - 1;
            if (xx < 0 || xx > 127) continue;
            s += w[ky * 3 + kx] * in[yy * 128 + xx];
        }
    }
    g_dwq[((size_t)b * C3 + ch) * HW + p] = s;
}

// ============================================================
// Partial Gram (48x48) + q/k squared-norm partials per (bh, n-chunk).
// Deterministic: partials written to g_part, reduced in a second kernel.
// ============================================================
__global__ __launch_bounds__(256) void gram_kernel()
{
    const int chunk = blockIdx.x;   // 0..127
    const int bh    = blockIdx.y;   // 0..31
    const int b = bh >> 2, h = bh & 3;
    const int n0 = chunk * NCHUNK;

    __shared__ float qs[48][NCHUNK];
    __shared__ float ks[48][NCHUNK];

    const float* qb = g_dwq + ((size_t)b * C3 + h * HC) * HW + n0;
    const float* kb = qb + (size_t)C_ * HW;

    const int tid = threadIdx.x;
    for (int i = tid; i < 48 * (NCHUNK / 4); i += 256) {
        const int r  = i >> 5;            // NCHUNK/4 == 32
        const int c4 = (i & 31) << 2;
        *(float4*)&qs[r][c4] = *(const float4*)&qb[(size_t)r * HW + c4];
        *(float4*)&ks[r][c4] = *(const float4*)&kb[(size_t)r * HW + c4];
    }
    __syncthreads();

    const int tc = tid >> 4;   // 0..15 -> c rows tc*3..tc*3+2
    const int td = tid & 15;   // 0..15 -> d rows td*3..td*3+2

    float acc[3][3];
#pragma unroll
    for (int i = 0; i < 3; i++)
#pragma unroll
        for (int j = 0; j < 3; j++) acc[i][j] = 0.f;
    float nqa[3] = {0.f, 0.f, 0.f};
    float nka[3] = {0.f, 0.f, 0.f};

    for (int n = 0; n < NCHUNK; n += 4) {
        float4 qv[3], kv[3];
#pragma unroll
        for (int i = 0; i < 3; i++) {
            qv[i] = *(float4*)&qs[tc * 3 + i][n];
            kv[i] = *(float4*)&ks[td * 3 + i][n];
        }
#pragma unroll
        for (int i = 0; i < 3; i++)
#pragma unroll
            for (int j = 0; j < 3; j++)
                acc[i][j] += qv[i].x * kv[j].x + qv[i].y * kv[j].y +
                             qv[i].z * kv[j].z + qv[i].w * kv[j].w;
        if (td == 0) {
#pragma unroll
            for (int i = 0; i < 3; i++)
                nqa[i] += qv[i].x * qv[i].x + qv[i].y * qv[i].y +
                          qv[i].z * qv[i].z + qv[i].w * qv[i].w;
        }
        if (tc == 0) {
#pragma unroll
            for (int j = 0; j < 3; j++)
                nka[j] += kv[j].x * kv[j].x + kv[j].y * kv[j].y +
                          kv[j].z * kv[j].z + kv[j].w * kv[j].w;
        }
    }

    float* out = g_part + ((size_t)chunk * 32 + bh) * PART_STRIDE;
#pragma unroll
    for (int i = 0; i < 3; i++)
#pragma unroll
        for (int j = 0; j < 3; j++)
            out[(tc * 3 + i) * 48 + td * 3 + j] = acc[i][j];
    if (td == 0) {
#pragma unroll
        for (int i = 0; i < 3; i++) out[2304 + tc * 3 + i] = nqa[i];
    }
    if (tc == 0) {
#pragma unroll
        for (int j = 0; j < 3; j++) out[2352 + td * 3 + j] = nka[j];
    }
}

__global__ __launch_bounds__(256) void reduce_kernel()
{
    const int idx = blockIdx.x * 256 + threadIdx.x;
    if (idx >= 32 * PART_STRIDE) return;
    const int bh = idx / PART_STRIDE;
    const int e  = idx % PART_STRIDE;
    const float* p = g_part + (size_t)bh * PART_STRIDE + e;
    float s = 0.f;
    for (int ch = 0; ch < NCHUNKS; ch++)
        s += p[(size_t)ch * 32 * PART_STRIDE];
    if (e < 2304)       g_gram[bh * 2304 + e]      = s;
    else if (e < 2352)  g_nq[bh * 48 + (e - 2304)] = s;
    else                g_nk[bh * 48 + (e - 2352)] = s;
}

// ============================================================
// Softmax over d: attn[c,d] = softmax( gram[c,d]*t / (||q_c||*||k_d||) )
// One warp per (bh, c) row.
// ============================================================
__global__ __launch_bounds__(32) void softmax_kernel(const float* __restrict__ temperature)
{
    const int row = blockIdx.x;           // 0..1535
    const int bh = row / 48, c = row % 48;
    const int h = bh & 3;
    const int lane = threadIdx.x;

    const float* g = g_gram + (bh * 48 + c) * 48;
    const float t = temperature[h];
    const float qn = fmaxf(sqrtf(g_nq[bh * 48 + c]), 1e-12f);
    const float sq = t / qn;

    float v0 = g[lane] * sq / fmaxf(sqrtf(g_nk[bh * 48 + lane]), 1e-12f);
    float v1 = -3.4e38f;
    if (lane < 16)
        v1 = g[lane + 32] * sq / fmaxf(sqrtf(g_nk[bh * 48 + lane + 32]), 1e-12f);

    float m = fmaxf(v0, v1);
#pragma unroll
    for (int o = 16; o; o >>= 1) m = fmaxf(m, __shfl_xor_sync(0xffffffffu, m, o));
    const float e0 = expf(v0 - m);
    const float e1 = (lane < 16) ? expf(v1 - m) : 0.f;
    float s = e0 + e1;
#pragma unroll
    for (int o = 16; o; o >>= 1) s += __shfl_xor_sync(0xffffffffu, s, o);
    const float inv = 1.f / s;

    float* a = g_attn + (bh * 48 + c) * 48;
    a[lane] = e0 * inv;
    if (lane < 16) a[lane + 32] = e1 * inv;
}

// ============================================================
// Weff[b][o][h*48+d] = sum_cc wproj[o][h*48+cc] * attn[b,h,cc,d]
// (fuses proj into the attn@V GEMM: out = Weff[b] @ V[b])
// ============================================================
__global__ __launch_bounds__(256) void weff_kernel(const float* __restrict__ wproj)
{
    const int idx = blockIdx.x * 256 + threadIdx.x;
    if (idx >= B_ * C_ * C_) return;
    const int b = idx / (C_ * C_);
    const int r = idx % (C_ * C_);
    const int o = r / C_;
    const int j = r % C_;
    const int h = j / HC, d = j % HC;

    const float* wp = wproj + o * C_ + h * HC;
    const float* at = g_attn + ((b * 4 + h) * 48) * 48 + d;
    float s = 0.f;
#pragma unroll 8
    for (int cc = 0; cc < 48; cc++)
        s += wp[cc] * at[cc * 48];
    g_weff[idx] = s;
}

// ============================================================
extern "C" void kernel_launch(void* const* d_in, const int* in_sizes, int n_in,
                              void* d_out, int out_size)
{
    // Map inputs defensively by element count (all counts are distinct).
    const float *x = nullptr, *w_qkv = nullptr, *w_dw = nullptr,
                *temperature = nullptr, *w_proj = nullptr;
    for (int i = 0; i < n_in; i++) {
        switch (in_sizes[i]) {
            case 25165824: x           = (const float*)d_in[i]; break;
            case 110592:   w_qkv       = (const float*)d_in[i]; break;
            case 5184:     w_dw        = (const float*)d_in[i]; break;
            case 4:        temperature = (const float*)d_in[i]; break;
            case 36864:    w_proj      = (const float*)d_in[i]; break;
        }
    }
    float* out = (float*)d_out;

    float *qkv, *dwq, *weff;
    cudaGetSymbolAddress((void**)&qkv,  g_qkv);
    cudaGetSymbolAddress((void**)&dwq,  g_dwq);
    cudaGetSymbolAddress((void**)&weff, g_weff);

    // 1) qkv[b] = W_qkv(576x192) @ x[b](192x16384)
    gemm96x128<<<dim3(HW / 128, C3 / 96, B_), 256>>>(
        w_qkv, x, qkv, C_, (size_t)0, (size_t)C_ * HW, (size_t)C3 * HW);

    // 2) depthwise 3x3
    dwconv_kernel<<<dim3(HW / 256, C3, B_), 256>>>(w_dw);

    // 3) Gram partials + norm partials (split-K, deterministic)
    gram_kernel<<<dim3(NCHUNKS, 32), 256>>>();

    // 4) reduce partials
    reduce_kernel<<<(32 * PART_STRIDE + 255) / 256, 256>>>();

    // 5) scaled softmax
    softmax_kernel<<<32 * 48, 32>>>(temperature);

    // 6) fold proj into attention: Weff = W_proj @ attn (per batch)
    weff_kernel<<<(B_ * C_ * C_ + 255) / 256, 256>>>(w_proj);

    // 7) out[b] = Weff[b](192x192) @ V[b](192x16384)
    gemm96x128<<<dim3(HW / 128, C_ / 96, B_), 256>>>(
        weff, dwq + (size_t)2 * C_ * HW, out, C_,
        (size_t)(C_ * C_), (size_t)C3 * HW, (size_t)C_ * HW);
}

// round 2
// speedup vs baseline: 1.9253x; 1.9253x over previous
#include <cuda_runtime.h>
#include <math.h>
#include <stdint.h>

#define B_      8
#define C_      192
#define C3      576
#define HW      16384
#define HEADS_  4
#define HC      48
#define NCHUNK  128
#define NCHUNKS2 32             // gram grid chunks (each covers 4*128 pixels)
#define PART_STRIDE 2400        // 2304 gram + 48 nq + 48 nk

// -------- device scratch (no allocations allowed) --------
__device__ float g_qkv [(size_t)B_ * C3 * HW];
__device__ float g_dwq [(size_t)B_ * C3 * HW];
__device__ float g_part[(size_t)NCHUNKS2 * 32 * PART_STRIDE];
__device__ float g_gram[32 * HC * HC];
__device__ float g_nq  [32 * HC];
__device__ float g_nk  [32 * HC];
__device__ float g_attn[32 * HC * HC];
__device__ float g_weff[B_ * C_ * C_];

// ============================================================
// tf32 helpers
// ============================================================
__device__ __forceinline__ float to_tf32(float x) {
    uint32_t u;
    asm("cvt.rna.tf32.f32 %0, %1;" : "=r"(u) : "f"(x));
    return __uint_as_float(u);
}

__device__ __forceinline__ void mma_tf32(float* d, const float* a, const float* b) {
    asm volatile(
        "mma.sync.aligned.m16n8k8.row.col.f32.tf32.tf32.f32 "
        "{%0,%1,%2,%3}, {%4,%5,%6,%7}, {%8,%9}, {%0,%1,%2,%3};\n"
        : "+f"(d[0]), "+f"(d[1]), "+f"(d[2]), "+f"(d[3])
        : "r"(__float_as_uint(a[0])), "r"(__float_as_uint(a[1])),
          "r"(__float_as_uint(a[2])), "r"(__float_as_uint(a[3])),
          "r"(__float_as_uint(b[0])), "r"(__float_as_uint(b[1])));
}

// ============================================================
// Tensor-core GEMM: C[b] = A[b] (MxK row) @ B[b] (KxN row), N = HW.
// BM=64 BN=128 BK=16, 256 threads, warps 2(M) x 4(N), each warp 32x32.
// M % 64 == 0, K % 16 == 0.
// ============================================================
#define BM 64
#define BN 128
#define BK 16
#define ASTR 72
#define BSTR 136

__global__ __launch_bounds__(256) void gemm_tf32(
    const float* __restrict__ A, const float* __restrict__ B,
    float* __restrict__ C, int K,
    size_t sAb, size_t sBb, size_t sCb)
{
    const int N = HW;
    A += (size_t)blockIdx.z * sAb;
    B += (size_t)blockIdx.z * sBb;
    C += (size_t)blockIdx.z * sCb;
    const int m0 = blockIdx.y * BM;
    const int n0 = blockIdx.x * BN;

    __shared__ float As[2][BK][ASTR];
    __shared__ float Bs[2][BK][BSTR];

    const int tid  = threadIdx.x;
    const int warp = tid >> 5;
    const int lane = tid & 31;
    const int wm = (warp & 1) * 32;
    const int wn = (warp >> 1) * 32;
    const int grp = lane >> 2;
    const int qd  = lane & 3;

    const int arow = tid >> 2;           // 0..63
    const int acol = (tid & 3) << 2;     // 0,4,8,12
    const int brow = tid >> 4;           // 0..15
    const int bcol = (tid & 15) << 3;    // 0..120

    float acc[2][4][4];
#pragma unroll
    for (int i = 0; i < 2; i++)
#pragma unroll
        for (int j = 0; j < 4; j++)
#pragma unroll
            for (int r = 0; r < 4; r++) acc[i][j][r] = 0.f;

    const int NK = K / BK;
    float4 aReg, bReg0, bReg1;

    // prologue load
    aReg  = *(const float4*)&A[(size_t)(m0 + arow) * K + acol];
    bReg0 = *(const float4*)&B[(size_t)brow * N + n0 + bcol];
    bReg1 = *(const float4*)&B[(size_t)brow * N + n0 + bcol + 4];
    {
        As[0][acol + 0][arow] = to_tf32(aReg.x);
        As[0][acol + 1][arow] = to_tf32(aReg.y);
        As[0][acol + 2][arow] = to_tf32(aReg.z);
        As[0][acol + 3][arow] = to_tf32(aReg.w);
        float4 t0 = make_float4(to_tf32(bReg0.x), to_tf32(bReg0.y), to_tf32(bReg0.z), to_tf32(bReg0.w));
        float4 t1 = make_float4(to_tf32(bReg1.x), to_tf32(bReg1.y), to_tf32(bReg1.z), to_tf32(bReg1.w));
        *(float4*)&Bs[0][brow][bcol]     = t0;
        *(float4*)&Bs[0][brow][bcol + 4] = t1;
    }
    __syncthreads();

    for (int it = 0; it < NK; it++) {
        const int cur = it & 1;
        if (it + 1 < NK) {
            const int k0 = (it + 1) * BK;
            aReg  = *(const float4*)&A[(size_t)(m0 + arow) * K + k0 + acol];
            bReg0 = *(const float4*)&B[(size_t)(k0 + brow) * N + n0 + bcol];
            bReg1 = *(const float4*)&B[(size_t)(k0 + brow) * N + n0 + bcol + 4];
        }

#pragma unroll
        for (int ks = 0; ks < 2; ks++) {
            const int kb = ks * 8;
            float af[2][4];
#pragma unroll
            for (int mt = 0; mt < 2; mt++) {
                const int m = wm + mt * 16 + grp;
                af[mt][0] = As[cur][kb + qd][m];
                af[mt][1] = As[cur][kb + qd][m + 8];
                af[mt][2] = As[cur][kb + qd + 4][m];
                af[mt][3] = As[cur][kb + qd + 4][m + 8];
            }
#pragma unroll
            for (int nt = 0; nt < 4; nt++) {
                float bf[2];
                const int n = wn + nt * 8 + grp;
                bf[0] = Bs[cur][kb + qd][n];
                bf[1] = Bs[cur][kb + qd + 4][n];
#pragma unroll
                for (int mt = 0; mt < 2; mt++)
                    mma_tf32(acc[mt][nt], af[mt], bf);
            }
        }

        if (it + 1 < NK) {
            const int nxt = (it + 1) & 1;
            As[nxt][acol + 0][arow] = to_tf32(aReg.x);
            As[nxt][acol + 1][arow] = to_tf32(aReg.y);
            As[nxt][acol + 2][arow] = to_tf32(aReg.z);
            As[nxt][acol + 3][arow] = to_tf32(aReg.w);
            float4 t0 = make_float4(to_tf32(bReg0.x), to_tf32(bReg0.y), to_tf32(bReg0.z), to_tf32(bReg0.w));
            float4 t1 = make_float4(to_tf32(bReg1.x), to_tf32(bReg1.y), to_tf32(bReg1.z), to_tf32(bReg1.w));
            *(float4*)&Bs[nxt][brow][bcol]     = t0;
            *(float4*)&Bs[nxt][brow][bcol + 4] = t1;
            __syncthreads();
        }
    }

#pragma unroll
    for (int mt = 0; mt < 2; mt++) {
#pragma unroll
        for (int nt = 0; nt < 4; nt++) {
            const int row = m0 + wm + mt * 16 + grp;
            const int col = n0 + wn + nt * 8 + qd * 2;
            *(float2*)&C[(size_t)row * N + col]       = make_float2(acc[mt][nt][0], acc[mt][nt][1]);
            *(float2*)&C[(size_t)(row + 8) * N + col] = make_float2(acc[mt][nt][2], acc[mt][nt][3]);
        }
    }
}

// ============================================================
// Depthwise 3x3 SAME: shared halo tile 66x130, rolling row-dots.
// grid (2, 576, 8): each block does a 64-row half of one (b,ch) image.
// ============================================================
__global__ __launch_bounds__(256) void dwconv_kernel(const float* __restrict__ wdw)
{
    __shared__ float s[66][130];

    const int half = blockIdx.x;    // 0,1
    const int ch   = blockIdx.y;    // 0..575
    const int b    = blockIdx.z;
    const int r0   = half * 64;

    const float* in = g_qkv + ((size_t)b * C3 + ch) * HW;
    float* outp = g_dwq + ((size_t)b * C3 + ch) * HW;
    const int tid = threadIdx.x;

    // zero side pads
    for (int r = tid; r < 66; r += 256) { s[r][0] = 0.f; s[r][129] = 0.f; }

    // load 66 rows (with top/bottom halo) into cols [1..128]
    for (int i = tid; i < 66 * 32; i += 256) {
        const int sr = i >> 5;
        const int c4 = (i & 31) << 2;
        const int gr = r0 - 1 + sr;
        float4 v = make_float4(0.f, 0.f, 0.f, 0.f);
        if (gr >= 0 && gr < 128) v = *(const float4*)&in[gr * 128 + c4];
        s[sr][1 + c4 + 0] = v.x;
        s[sr][1 + c4 + 1] = v.y;
        s[sr][1 + c4 + 2] = v.z;
        s[sr][1 + c4 + 3] = v.w;
    }
    __syncthreads();

    float w[9];
#pragma unroll
    for (int i = 0; i < 9; i++) w[i] = __ldg(&wdw[ch * 9 + i]);

    const int lane = tid & 31;
    const int rb   = tid >> 5;   // 0..7 -> rows rb*8..rb*8+7 (local in half)

#pragma unroll
    for (int seg = 0; seg < 4; seg++) {
        const int c = lane + seg * 32;   // global col; smem cols c..c+2
        float o[8];
#pragma unroll
        for (int rr = 0; rr < 10; rr++) {
            const int sr = rb * 8 + rr;
            const float v0 = s[sr][c];
            const float v1 = s[sr][c + 1];
            const float v2 = s[sr][c + 2];
            const float d0 = w[0] * v0 + w[1] * v1 + w[2] * v2;
            const float d1 = w[3] * v0 + w[4] * v1 + w[5] * v2;
            const float d2 = w[6] * v0 + w[7] * v1 + w[8] * v2;
            if (rr < 8)             o[rr]     = d0;
            if (rr >= 1 && rr <= 8) o[rr - 1] += d1;
            if (rr >= 2)            o[rr - 2] += d2;
        }
#pragma unroll
        for (int y = 0; y < 8; y++)
            outp[(r0 + rb * 8 + y) * 128 + c] = o[y];
    }
}

// ============================================================
// Partial Gram (48x48) + q/k norm partials. grid (32, 32),
// each block accumulates 4 sub-chunks of 128 pixels.
// ============================================================
__global__ __launch_bounds__(256) void gram_kernel()
{
    const int chunk = blockIdx.x;   // 0..31
    const int bh    = blockIdx.y;   // 0..31
    const int b = bh >> 2, h = bh & 3;

    __shared__ float qs[48][NCHUNK];
    __shared__ float ks[48][NCHUNK];

    const float* qbase = g_dwq + ((size_t)b * C3 + h * HC) * HW;
    const float* kbase = qbase + (size_t)C_ * HW;

    const int tid = threadIdx.x;
    const int tc = tid >> 4;
    const int td = tid & 15;

    float acc[3][3];
#pragma unroll
    for (int i = 0; i < 3; i++)
#pragma unroll
        for (int j = 0; j < 3; j++) acc[i][j] = 0.f;
    float nqa[3] = {0.f, 0.f, 0.f};
    float nka[3] = {0.f, 0.f, 0.f};

    for (int sub = 0; sub < 4; sub++) {
        const int n0 = (chunk * 4 + sub) * NCHUNK;
        const float* qb = qbase + n0;
        const float* kb = kbase + n0;

        __syncthreads();
        for (int i = tid; i < 48 * (NCHUNK / 4); i += 256) {
            const int r  = i >> 5;
            const int c4 = (i & 31) << 2;
            *(float4*)&qs[r][c4] = *(const float4*)&qb[(size_t)r * HW + c4];
            *(float4*)&ks[r][c4] = *(const float4*)&kb[(size_t)r * HW + c4];
        }
        __syncthreads();

        for (int n = 0; n < NCHUNK; n += 4) {
            float4 qv[3], kv[3];
#pragma unroll
            for (int i = 0; i < 3; i++) {
                qv[i] = *(float4*)&qs[tc * 3 + i][n];
                kv[i] = *(float4*)&ks[td * 3 + i][n];
            }
#pragma unroll
            for (int i = 0; i < 3; i++)
#pragma unroll
                for (int j = 0; j < 3; j++)
                    acc[i][j] += qv[i].x * kv[j].x + qv[i].y * kv[j].y +
                                 qv[i].z * kv[j].z + qv[i].w * kv[j].w;
            if (td == 0) {
#pragma unroll
                for (int i = 0; i < 3; i++)
                    nqa[i] += qv[i].x * qv[i].x + qv[i].y * qv[i].y +
                              qv[i].z * qv[i].z + qv[i].w * qv[i].w;
            }
            if (tc == 0) {
#pragma unroll
                for (int j = 0; j < 3; j++)
                    nka[j] += kv[j].x * kv[j].x + kv[j].y * kv[j].y +
                              kv[j].z * kv[j].z + kv[j].w * kv[j].w;
            }
        }
    }

    float* out = g_part + ((size_t)chunk * 32 + bh) * PART_STRIDE;
#pragma unroll
    for (int i = 0; i < 3; i++)
#pragma unroll
        for (int j = 0; j < 3; j++)
            out[(tc * 3 + i) * 48 + td * 3 + j] = acc[i][j];
    if (td == 0) {
#pragma unroll
        for (int i = 0; i < 3; i++) out[2304 + tc * 3 + i] = nqa[i];
    }
    if (tc == 0) {
#pragma unroll
        for (int j = 0; j < 3; j++) out[2352 + td * 3 + j] = nka[j];
    }
}

__global__ __launch_bounds__(256) void reduce_kernel()
{
    const int idx = blockIdx.x * 256 + threadIdx.x;
    if (idx >= 32 * PART_STRIDE) return;
    const int bh = idx / PART_STRIDE;
    const int e  = idx % PART_STRIDE;
    const float* p = g_part + (size_t)bh * PART_STRIDE + e;
    float s = 0.f;
    for (int ch = 0; ch < NCHUNKS2; ch++)
        s += p[(size_t)ch * 32 * PART_STRIDE];
    if (e < 2304)       g_gram[bh * 2304 + e]      = s;
    else if (e < 2352)  g_nq[bh * 48 + (e - 2304)] = s;
    else                g_nk[bh * 48 + (e - 2352)] = s;
}

// ============================================================
// Softmax over d with folded q/k norms + temperature.
// ============================================================
__global__ __launch_bounds__(32) void softmax_kernel(const float* __restrict__ temperature)
{
    const int row = blockIdx.x;
    const int bh = row / 48, c = row % 48;
    const int h = bh & 3;
    const int lane = threadIdx.x;

    const float* g = g_gram + (bh * 48 + c) * 48;
    const float t = temperature[h];
    const float qn = fmaxf(sqrtf(g_nq[bh * 48 + c]), 1e-12f);
    const float sq = t / qn;

    float v0 = g[lane] * sq / fmaxf(sqrtf(g_nk[bh * 48 + lane]), 1e-12f);
    float v1 = -3.4e38f;
    if (lane < 16)
        v1 = g[lane + 32] * sq / fmaxf(sqrtf(g_nk[bh * 48 + lane + 32]), 1e-12f);

    float m = fmaxf(v0, v1);
#pragma unroll
    for (int o = 16; o; o >>= 1) m = fmaxf(m, __shfl_xor_sync(0xffffffffu, m, o));
    const float e0 = expf(v0 - m);
    const float e1 = (lane < 16) ? expf(v1 - m) : 0.f;
    float s = e0 + e1;
#pragma unroll
    for (int o = 16; o; o >>= 1) s += __shfl_xor_sync(0xffffffffu, s, o);
    const float inv = 1.f / s;

    float* a = g_attn + (bh * 48 + c) * 48;
    a[lane] = e0 * inv;
    if (lane < 16) a[lane + 32] = e1 * inv;
}

// ============================================================
// Weff[b][o][h*48+d] = sum_cc wproj[o][h*48+cc] * attn[b,h,cc,d]
// ============================================================
__global__ __launch_bounds__(256) void weff_kernel(const float* __restrict__ wproj)
{
    const int idx = blockIdx.x * 256 + threadIdx.x;
    if (idx >= B_ * C_ * C_) return;
    const int b = idx / (C_ * C_);
    const int r = idx % (C_ * C_);
    const int o = r / C_;
    const int j = r % C_;
    const int h = j / HC, d = j % HC;

    const float* wp = wproj + o * C_ + h * HC;
    const float* at = g_attn + ((b * 4 + h) * 48) * 48 + d;
    float s = 0.f;
#pragma unroll 8
    for (int cc = 0; cc < 48; cc++)
        s += wp[cc] * at[cc * 48];
    g_weff[idx] = s;
}

// ============================================================
extern "C" void kernel_launch(void* const* d_in, const int* in_sizes, int n_in,
                              void* d_out, int out_size)
{
    const float *x = nullptr, *w_qkv = nullptr, *w_dw = nullptr,
                *temperature = nullptr, *w_proj = nullptr;
    for (int i = 0; i < n_in; i++) {
        switch (in_sizes[i]) {
            case 25165824: x           = (const float*)d_in[i]; break;
            case 110592:   w_qkv       = (const float*)d_in[i]; break;
            case 5184:     w_dw        = (const float*)d_in[i]; break;
            case 4:        temperature = (const float*)d_in[i]; break;
            case 36864:    w_proj      = (const float*)d_in[i]; break;
        }
    }
    float* out = (float*)d_out;

    float *qkv, *weff, *dwq;
    cudaGetSymbolAddress((void**)&qkv,  g_qkv);
    cudaGetSymbolAddress((void**)&dwq,  g_dwq);
    cudaGetSymbolAddress((void**)&weff, g_weff);

    // 1) qkv[b] = W_qkv(576x192) @ x[b](192x16384)   (tensor cores, tf32)
    gemm_tf32<<<dim3(HW / BN, C3 / BM, B_), 256>>>(
        w_qkv, x, qkv, C_, (size_t)0, (size_t)C_ * HW, (size_t)C3 * HW);

    // 2) depthwise 3x3
    dwconv_kernel<<<dim3(2, C3, B_), 256>>>(w_dw);

    // 3) Gram + norm partials (split-K x32, deterministic)
    gram_kernel<<<dim3(NCHUNKS2, 32), 256>>>();

    // 4) reduce partials
    reduce_kernel<<<(32 * PART_STRIDE + 255) / 256, 256>>>();

    // 5) scaled softmax
    softmax_kernel<<<32 * 48, 32>>>(temperature);

    // 6) Weff = W_proj @ attn (fold projection into attn@V)
    weff_kernel<<<(B_ * C_ * C_ + 255) / 256, 256>>>(w_proj);

    // 7) out[b] = Weff[b](192x192) @ V[b](192x16384)  (tensor cores, tf32)
    gemm_tf32<<<dim3(HW / BN, C_ / BM, B_), 256>>>(
        weff, dwq + (size_t)2 * C_ * HW, out, C_,
        (size_t)(C_ * C_), (size_t)C3 * HW, (size_t)C_ * HW);
}